// round 17
// baseline (speedup 1.0000x reference)
#include <cuda_runtime.h>
#include <cuda_fp16.h>
#include <math.h>

// ---------------------------------------------------------------------------
// Problem constants
// ---------------------------------------------------------------------------
#define BB     128
#define TSTEPS 31
#define NCLS   111
#define NPOS   256          // H*W = 8*32
#define CONV_KT 72          // 4608 / 64
#define CHAIN_BLOCKS 128u   // 64 blocks per LSTM lane (cell0 / cell1)

// ---------------------------------------------------------------------------
// Scratch: one __device__ global array (no runtime allocation allowed)
// ---------------------------------------------------------------------------
#define OF_FPROJ  0u          // 32768*512       = 16777216
#define OF_EK0    16777216u   // 112*2048        = 229376
#define OF_ST     17006592u   // 8 * 65536       = 524288
#define OF_H1ALL  17530880u   // 31*65536        = 2031616
#define OF_HP     19562496u   // 31*65536        = 2031616
#define OF_ATT    21594112u   // 31*128*256      = 1015808
#define OF_GLIM   22609920u   // 31*65536        = 2031616
#define OF_WT     24641536u   // 4 * 2048*512 half = 2097152 floats used
#define OF_FH     28835840u   // 16.7M half      = 8388608 floats
#define OF_WTH    37224448u   // 512*4608 half   = 1179648 floats
#define SCRATCH_TOTAL 38404096u
__device__ float g_scratch[SCRATCH_TOTAL];

// grid barrier state (monotone generation; robust across graph replays)
__device__ unsigned g_cnt = 0;
__device__ volatile unsigned g_gen = 0;

// ---------------------------------------------------------------------------
// Helpers
// ---------------------------------------------------------------------------
__device__ __forceinline__ float fast_tanh(float x) {
    float r; asm("tanh.approx.f32 %0, %1;" : "=f"(r) : "f"(x));
    return r;
}
__device__ __forceinline__ void mma_tf32(float* d, const unsigned* a, const unsigned* b) {
    asm volatile(
        "mma.sync.aligned.m16n8k8.row.col.f32.tf32.tf32.f32 "
        "{%0,%1,%2,%3}, {%4,%5,%6,%7}, {%8,%9}, {%0,%1,%2,%3};\n"
        : "+f"(d[0]), "+f"(d[1]), "+f"(d[2]), "+f"(d[3])
        : "r"(a[0]), "r"(a[1]), "r"(a[2]), "r"(a[3]), "r"(b[0]), "r"(b[1]));
}
__device__ __forceinline__ void mma_fp16(float* d, const unsigned* a, const unsigned* b) {
    asm volatile(
        "mma.sync.aligned.m16n8k16.row.col.f32.f16.f16.f32 "
        "{%0,%1,%2,%3}, {%4,%5,%6,%7}, {%8,%9}, {%0,%1,%2,%3};\n"
        : "+f"(d[0]), "+f"(d[1]), "+f"(d[2]), "+f"(d[3])
        : "r"(a[0]), "r"(a[1]), "r"(a[2]), "r"(a[3]), "r"(b[0]), "r"(b[1]));
}
__device__ __forceinline__ void ldsm4(unsigned* r, unsigned addr) {
    asm volatile("ldmatrix.sync.aligned.m8n8.x4.shared.b16 {%0,%1,%2,%3}, [%4];"
                 : "=r"(r[0]), "=r"(r[1]), "=r"(r[2]), "=r"(r[3]) : "r"(addr));
}
__device__ __forceinline__ void cp16(float* dst, const float* src, bool v) {
    unsigned d = (unsigned)__cvta_generic_to_shared(dst);
    int sz = v ? 16 : 0;
    asm volatile("cp.async.ca.shared.global [%0], [%1], 16, %2;\n"
                 :: "r"(d), "l"(src), "r"(sz));
}
__device__ __forceinline__ void cpA(unsigned dst, const void* src, bool v) {
    int sz = v ? 16 : 0;
    asm volatile("cp.async.ca.shared.global [%0], [%1], 16, %2;\n"
                 :: "r"(dst), "l"(src), "r"(sz));
}
#define CP_COMMIT() asm volatile("cp.async.commit_group;\n" ::: "memory")
#define CP_WAIT(n)  asm volatile("cp.async.wait_group %0;\n" :: "n"(n) : "memory")

__device__ __forceinline__ void grid_sync() {
    __syncthreads();
    if (threadIdx.x == 0) {
        __threadfence();
        const unsigned gen = g_gen;
        if (atomicAdd(&g_cnt, 1u) == CHAIN_BLOCKS - 1u) {
            g_cnt = 0;
            __threadfence();
            g_gen = gen + 1u;
        } else {
            while (g_gen == gen) { __nanosleep(32); }
        }
        __threadfence();
    }
    __syncthreads();
}

// ---------------------------------------------------------------------------
// Ek0[s][n] = sum_k embed_W[s][k] * k0[k][n] ; row 111 = zeros (SOS). fp32.
// ---------------------------------------------------------------------------
__global__ __launch_bounds__(256) void ek0_kernel(
    const float* __restrict__ eW, const float* __restrict__ k0,
    float* __restrict__ Ek0)
{
    const int n = blockIdx.x * 256 + threadIdx.x;
    const int s = blockIdx.y;
    float a0 = 0.f, a1 = 0.f, a2 = 0.f, a3 = 0.f;
    if (s < 111) {
        const float* e = eW + s * 512;
        for (int k = 0; k < 512; k += 4) {
            a0 += e[k + 0] * k0[(size_t)(k + 0) * 2048 + n];
            a1 += e[k + 1] * k0[(size_t)(k + 1) * 2048 + n];
            a2 += e[k + 2] * k0[(size_t)(k + 2) * 2048 + n];
            a3 += e[k + 3] * k0[(size_t)(k + 3) * 2048 + n];
        }
    }
    Ek0[(size_t)s * 2048 + n] = (a0 + a1) + (a2 + a3);
}

// ---------------------------------------------------------------------------
// Reorder 4 LSTM weight matrices to fp16, gate-interleaved AND transposed:
//   Wt'[w][n'][k] = half(src[k][g*512+j]), n' = j*4+g.  grid (2048, 4).
// ---------------------------------------------------------------------------
__global__ __launch_bounds__(256) void reorder_w4h(
    const float* __restrict__ k0, const float* __restrict__ rk0,
    const float* __restrict__ k1, const float* __restrict__ rk1,
    __half* __restrict__ out)
{
    const int np = blockIdx.x;           // n' 0..2047
    const int w = blockIdx.y;
    const float* src = (w == 0) ? k0 : (w == 1) ? rk0 : (w == 2) ? k1 : rk1;
    __half* dst = out + (size_t)w * 1048576 + (size_t)np * 512;
    const int g = np & 3, j = np >> 2;
    for (int k = threadIdx.x; k < 512; k += 256)
        dst[k] = __float2half(src[(size_t)k * 2048 + g * 512 + j]);
}

// ---------------------------------------------------------------------------
// Prep for fp16 conv: Fh = half(features) elementwise; Wth[n][k] = half(Wf[k][n])
// grid 65536 + 2304 (transpose tiles 32x32), 256 threads
// ---------------------------------------------------------------------------
__global__ __launch_bounds__(256) void prep_half(
    const float* __restrict__ F, const float* __restrict__ Wf,
    __half* __restrict__ Fh, __half* __restrict__ Wth)
{
    const int bid = blockIdx.x;
    const int tid = threadIdx.x;
    if (bid < 65536) {
        const int i = bid * 256 + tid;
        Fh[i] = __float2half(F[i]);
    } else {
        __shared__ float t[32][33];
        const int b2 = bid - 65536;              // 0..2303
        const int kb = (b2 % 144) * 32;
        const int nb = (b2 / 144) * 32;
        const int x = tid & 31, y = tid >> 5;    // 32 x 8
#pragma unroll
        for (int j = 0; j < 4; j++)
            t[y + j * 8][x] = Wf[(size_t)(kb + y + j * 8) * 512 + nb + x];
        __syncthreads();
#pragma unroll
        for (int j = 0; j < 4; j++)
            Wth[(size_t)(nb + y + j * 8) * 4608 + kb + x] = __float2half(t[x][y + j * 8]);
    }
}

// ---------------------------------------------------------------------------
// Conv device body: fp16 m16n8k16, BK=64, 3-stage cp.async, ldmatrix frag
// loads. Tile 128x128, 256 thr (8 warps 2m x 4n, warp tile 64x32).
// smem per stage: A [128][72 halves] + B [128][72] (144B pitch, LDSM
// conflict-free). 3 stages x 2 x 18432 = 110592 bytes.
// cid in [0,1024): nBase = (cid&3)*128, mBase = (cid>>2)*128.
// ---------------------------------------------------------------------------
#define CONV_SMEM 110592
__device__ void conv_body(
    __half* smh, int cid,
    const __half* __restrict__ Fh, const __half* __restrict__ Wth,
    const float* __restrict__ bf, float* __restrict__ fproj)
{
    const int tid = threadIdx.x;
    const int lane = tid & 31, warp = tid >> 5;
    const int wm = warp >> 2, wn = warp & 3;
    const int gid = lane >> 2, tig = lane & 3;
    const int nBase = (cid & 3) * 128;
    const int mBase = (cid >> 2) * 128;
    const unsigned smem_base = (unsigned)__cvta_generic_to_shared(smh);

    // loader: thread -> (row = tid>>1, 4 chunks q = (tid&1)*4 + j)
    const int lrow = tid >> 1;
    const int lq0 = (tid & 1) * 4;
    const int gm = mBase + lrow;
    const int ab = gm >> 8, ah = (gm >> 5) & 7, aw = gm & 31;

    auto issue = [&](int kt, int s) {
        const int r = kt >> 3;                 // kh*3+kw (64-k tile never crosses ci)
        const int ci0 = (kt & 7) << 6;
        const int kh = r / 3;
        const int kw = r - kh * 3;
        const int ih = ah + kh - 1, iw = aw + kw - 1;
        const bool v = ((unsigned)ih < 8u) && ((unsigned)iw < 32u);
        const unsigned As = smem_base + (unsigned)s * 18432u;
        const unsigned Bs = smem_base + 55296u + (unsigned)s * 18432u;
        const __half* pa = Fh + (((size_t)((ab * 8 + ih) * 32 + iw)) << 9) + ci0;
        const __half* pb = Wth + (size_t)(nBase + lrow) * 4608 + kt * 64;
#pragma unroll
        for (int j = 0; j < 4; j++) {
            const int q = lq0 + j;
            cpA(As + (unsigned)(lrow * 144 + q * 16), pa + q * 8, v);
            cpA(Bs + (unsigned)(lrow * 144 + q * 16), pb + q * 8, true);
        }
    };

    // ldmatrix lane-address offsets (bytes), constant across tiles
    unsigned aoff[4], boff[2];
    {
        const int arow = wm * 64 + (lane & 15);
        const unsigned acol = ((lane >> 4) & 1) * 16;   // 8 halves
#pragma unroll
        for (int mf = 0; mf < 4; mf++)
            aoff[mf] = (unsigned)((arow + mf * 16) * 144) + acol;
        const int brow = wn * 32 + ((lane >> 4) & 1) * 8 + (lane & 7);
        const unsigned bcol = (unsigned)(lane & 8) * 2;  // 0 or 16 bytes
        boff[0] = (unsigned)(brow * 144) + bcol;
        boff[1] = (unsigned)((brow + 16) * 144) + bcol;
    }

    float acc[4][4][4];
#pragma unroll
    for (int i = 0; i < 4; i++)
#pragma unroll
        for (int j = 0; j < 4; j++)
#pragma unroll
            for (int c = 0; c < 4; c++) acc[i][j][c] = 0.f;

    issue(0, 0); CP_COMMIT();
    issue(1, 1); CP_COMMIT();
    issue(2, 2); CP_COMMIT();

    for (int kt = 0; kt < CONV_KT; kt++) {
        const int s = kt % 3;
        if (kt < CONV_KT - 2)       { CP_WAIT(2); }
        else if (kt == CONV_KT - 2) { CP_WAIT(1); }
        else                        { CP_WAIT(0); }
        __syncthreads();

        const unsigned As = smem_base + (unsigned)s * 18432u;
        const unsigned Bs = smem_base + 55296u + (unsigned)s * 18432u;
#pragma unroll
        for (int ks = 0; ks < 4; ks++) {
            unsigned af[4][4], bfr[2][4];
#pragma unroll
            for (int mf = 0; mf < 4; mf++)
                ldsm4(af[mf], As + aoff[mf] + ks * 32);
#pragma unroll
            for (int nfp = 0; nfp < 2; nfp++)
                ldsm4(bfr[nfp], Bs + boff[nfp] + ks * 32);
#pragma unroll
            for (int mf = 0; mf < 4; mf++)
#pragma unroll
                for (int nf = 0; nf < 4; nf++)
                    mma_fp16(acc[mf][nf], af[mf], &bfr[nf >> 1][(nf & 1) * 2]);
        }
        __syncthreads();
        if (kt + 3 < CONV_KT) { issue(kt + 3, s); CP_COMMIT(); }
    }

#pragma unroll
    for (int mf = 0; mf < 4; mf++) {
        const int row = mBase + wm * 64 + mf * 16 + gid;
#pragma unroll
        for (int nf = 0; nf < 4; nf++) {
            const int col = nBase + wn * 32 + nf * 8 + tig * 2;
            const float bb0 = bf[col], bb1 = bf[col + 1];
            fproj[(size_t)row * 512 + col]           = acc[mf][nf][0] + bb0;
            fproj[(size_t)row * 512 + col + 1]       = acc[mf][nf][1] + bb1;
            fproj[(size_t)(row + 8) * 512 + col]     = acc[mf][nf][2] + bb0;
            fproj[(size_t)(row + 8) * 512 + col + 1] = acc[mf][nf][3] + bb1;
        }
    }
}

// ---------------------------------------------------------------------------
// fp16 LSTM cell (unchanged from R16): Z[64m x 64n'], BK=32, m16n8k16.
// ---------------------------------------------------------------------------
struct ChainShH {
    __half As[64][40];   // [m][k], pitch 40 halves
    __half Bs[64][40];   // [n'][k]
    float  Zs[64][68];
};

__device__ void lstm_cellh(
    ChainShH* sh, int nTile, int mTile,
    const float* __restrict__ Ek0, const int* __restrict__ gt, int tstep,
    const float* __restrict__ X1, const __half* __restrict__ W1t,
    const float* __restrict__ X2, const __half* __restrict__ W2t,
    const float* __restrict__ bias, const float* __restrict__ c_in,
    float* __restrict__ h_out, float* __restrict__ c_out,
    float* __restrict__ h_out2)
{
    const int tid = threadIdx.x;
    const int lane = tid & 31, warp = tid >> 5;
    const int wmm = (warp >> 2);            // 0..1
    const int wnn = (warp & 3);             // 0..3
    const int gid = lane >> 2, tig = lane & 3;
    const int nBase = nTile * 64;
    const int mBase = mTile * 64;

    const int lm = tid >> 2;                // loader row 0..63
    const int lq = (tid & 3) * 8;           // k offset within 32 (0,8,16,24)

    const int Ktot = X2 ? 1024 : 512;

    float acc[2][2][4];
#pragma unroll
    for (int i = 0; i < 2; i++)
#pragma unroll
        for (int j = 0; j < 2; j++)
#pragma unroll
            for (int c = 0; c < 4; c++) acc[i][j][c] = 0.f;

    float4 a0, a1; uint4 bW;
    a0 = *(const float4*)(X1 + (size_t)(mBase + lm) * 512 + lq);
    a1 = *(const float4*)(X1 + (size_t)(mBase + lm) * 512 + lq + 4);
    bW = *(const uint4*)(W1t + (size_t)(nBase + lm) * 512 + lq);

    for (int kt = 0; kt < Ktot; kt += 32) {
        __syncthreads();
        {
            unsigned p0, p1, p2, p3;
            asm("cvt.rn.f16x2.f32 %0, %1, %2;" : "=r"(p0) : "f"(a0.y), "f"(a0.x));
            asm("cvt.rn.f16x2.f32 %0, %1, %2;" : "=r"(p1) : "f"(a0.w), "f"(a0.z));
            asm("cvt.rn.f16x2.f32 %0, %1, %2;" : "=r"(p2) : "f"(a1.y), "f"(a1.x));
            asm("cvt.rn.f16x2.f32 %0, %1, %2;" : "=r"(p3) : "f"(a1.w), "f"(a1.z));
            uint4 av; av.x = p0; av.y = p1; av.z = p2; av.w = p3;
            *(uint4*)&sh->As[lm][lq] = av;
            *(uint4*)&sh->Bs[lm][lq] = bW;
        }
        __syncthreads();

        const int kn = kt + 32;
        if (kn < Ktot) {
            const float*  X = (kn < 512) ? X1 : X2;
            const __half* W = (kn < 512) ? W1t : W2t;
            const int kk = kn & 511;
            a0 = *(const float4*)(X + (size_t)(mBase + lm) * 512 + kk + lq);
            a1 = *(const float4*)(X + (size_t)(mBase + lm) * 512 + kk + lq + 4);
            bW = *(const uint4*)(W + (size_t)(nBase + lm) * 512 + kk + lq);
        }

#pragma unroll
        for (int ks = 0; ks < 2; ks++) {
            unsigned af[2][4], bf2[2][2];
#pragma unroll
            for (int mf = 0; mf < 2; mf++) {
                const int m0 = wmm * 32 + mf * 16 + gid;
                const __half* ap  = &sh->As[m0][ks * 16];
                const __half* ap8 = &sh->As[m0 + 8][ks * 16];
                af[mf][0] = *(const unsigned*)(ap  + tig * 2);
                af[mf][1] = *(const unsigned*)(ap8 + tig * 2);
                af[mf][2] = *(const unsigned*)(ap  + 8 + tig * 2);
                af[mf][3] = *(const unsigned*)(ap8 + 8 + tig * 2);
            }
#pragma unroll
            for (int nf = 0; nf < 2; nf++) {
                const int n0 = wnn * 16 + nf * 8 + gid;
                const __half* bp = &sh->Bs[n0][ks * 16];
                bf2[nf][0] = *(const unsigned*)(bp + tig * 2);
                bf2[nf][1] = *(const unsigned*)(bp + 8 + tig * 2);
            }
#pragma unroll
            for (int mf = 0; mf < 2; mf++)
#pragma unroll
                for (int nf = 0; nf < 2; nf++)
                    mma_fp16(acc[mf][nf], af[mf], bf2[nf]);
        }
    }

    __syncthreads();
#pragma unroll
    for (int mf = 0; mf < 2; mf++) {
        const int row = wmm * 32 + mf * 16 + gid;
#pragma unroll
        for (int nf = 0; nf < 2; nf++) {
            const int col = wnn * 16 + nf * 8 + tig * 2;
            sh->Zs[row][col]         = acc[mf][nf][0];
            sh->Zs[row][col + 1]     = acc[mf][nf][1];
            sh->Zs[row + 8][col]     = acc[mf][nf][2];
            sh->Zs[row + 8][col + 1] = acc[mf][nf][3];
        }
    }
    __syncthreads();

    const int r  = tid >> 2;
    const int j0 = (tid & 3) * 4;
    const int gr = mBase + r;
    int sym = 0;
    if (Ek0) sym = (tstep == 0) ? 111 : gt[gr * TSTEPS + tstep - 1];

#pragma unroll
    for (int jj = 0; jj < 4; jj++) {
        const int j  = j0 + jj;
        const int jg = nTile * 16 + j;
        float zi = sh->Zs[r][j * 4 + 0] + bias[jg];
        float zf = sh->Zs[r][j * 4 + 1] + bias[512 + jg];
        float zg = sh->Zs[r][j * 4 + 2] + bias[1024 + jg];
        float zo = sh->Zs[r][j * 4 + 3] + bias[1536 + jg];
        if (Ek0) {
            const float* e = Ek0 + (size_t)sym * 2048;
            zi += e[jg]; zf += e[512 + jg]; zg += e[1024 + jg]; zo += e[1536 + jg];
        }
        const float ci = c_in ? c_in[(size_t)gr * 512 + jg] : 0.f;
        const float si = 1.f / (1.f + expf(-zi));
        const float sf = 1.f / (1.f + expf(-zf));
        const float so = 1.f / (1.f + expf(-zo));
        const float c2 = sf * ci + si * tanhf(zg);
        const float h2 = so * tanhf(c2);
        h_out[(size_t)gr * 512 + jg] = h2;
        c_out[(size_t)gr * 512 + jg] = c2;
        if (h_out2) h_out2[(size_t)gr * 512 + jg] = h2;
    }
}

// ---------------------------------------------------------------------------
// Two-lane pipelined chain (unchanged from R16): 33 phases.
// ---------------------------------------------------------------------------
__device__ void chain_body(
    ChainShH* sh, int cbid,
    const float* __restrict__ Ek0, const int* __restrict__ gt,
    const float* __restrict__ hol,
    const __half* __restrict__ k0t, const __half* __restrict__ rk0t,
    const __half* __restrict__ k1t, const __half* __restrict__ rk1t,
    const float* __restrict__ b0, const float* __restrict__ b1,
    float* __restrict__ st, float* __restrict__ h1all)
{
    const int clane = cbid >> 6;     // 0 = cell0 lane, 1 = cell1 lane
    const int u = cbid & 63;
    const int nTile = u & 31, mTile = u >> 5;
    float* h0b[2] = { st,          st + 65536 };
    float* c0b[2] = { st + 131072, st + 196608 };
    float* h1b[2] = { st + 262144, st + 327680 };
    float* c1b[2] = { st + 393216, st + 458752 };

    for (int p = 0; p <= 32; p++) {
        if (clane == 0) {
            if (p == 0) {
                lstm_cellh(sh, nTile, mTile, nullptr, nullptr, 0,
                           hol, k0t, nullptr, nullptr, b0, nullptr,
                           h0b[1], c0b[1], nullptr);
            } else if (p <= 31) {
                const int t = p - 1;
                lstm_cellh(sh, nTile, mTile, Ek0, gt, t,
                           h0b[(t + 1) & 1], rk0t, nullptr, nullptr, b0,
                           c0b[(t + 1) & 1], h0b[t & 1], c0b[t & 1], nullptr);
            }
        } else {
            if (p == 1) {
                lstm_cellh(sh, nTile, mTile, nullptr, nullptr, 0,
                           h0b[1], k1t, nullptr, nullptr, b1, nullptr,
                           h1b[1], c1b[1], nullptr);
            } else if (p >= 2) {
                const int t = p - 2;
                lstm_cellh(sh, nTile, mTile, nullptr, nullptr, 0,
                           h0b[t & 1], k1t, h1b[(t + 1) & 1], rk1t, b1,
                           c1b[(t + 1) & 1], h1b[t & 1], c1b[t & 1],
                           h1all + (size_t)t * BB * 512);
            }
        }
        if (p < 32) grid_sync();
    }
}

// ---------------------------------------------------------------------------
// Fused kernel: bids 0..127 = pipelined LSTM chain (wave-1 resident -> grid
// barrier safe); bids 128..1151 = fp16 conv. Overlap on the chip.
// ---------------------------------------------------------------------------
__global__ __launch_bounds__(256, 2) void fused_conv_chain(
    const __half* __restrict__ Fh, const __half* __restrict__ Wth,
    const float* __restrict__ bf, float* __restrict__ fproj,
    const float* __restrict__ Ek0, const int* __restrict__ gt,
    const float* __restrict__ hol,
    const __half* __restrict__ k0t, const __half* __restrict__ rk0t,
    const __half* __restrict__ k1t, const __half* __restrict__ rk1t,
    const float* __restrict__ b0, const float* __restrict__ b1,
    float* __restrict__ st, float* __restrict__ h1all)
{
    extern __shared__ float smx[];
    if (blockIdx.x < (int)CHAIN_BLOCKS) {
        chain_body((ChainShH*)smx, blockIdx.x, Ek0, gt, hol,
                   k0t, rk0t, k1t, rk1t, b0, b1, st, h1all);
    } else {
        conv_body((__half*)smx, blockIdx.x - (int)CHAIN_BLOCKS, Fh, Wth, bf, fproj);
    }
}

// ---------------------------------------------------------------------------
// tf32 mma GEMM for hp = h1all @ Wh.  M=3968, N=512, K=512.
// ---------------------------------------------------------------------------
__device__ __forceinline__ float tf32r(float x) {
    unsigned u; asm("cvt.rna.tf32.f32 %0, %1;" : "=r"(u) : "f"(x));
    return __uint_as_float(u);
}
__global__ __launch_bounds__(256) void gemm_tc(
    const float* __restrict__ A, const float* __restrict__ W,
    float* __restrict__ C)
{
    __shared__ float As[2][128][20];
    __shared__ float Bs[2][16][132];

    const int tid = threadIdx.x;
    const int lane = tid & 31, warp = tid >> 5;
    const int wm = warp >> 2, wn = warp & 3;
    const int gid = lane >> 2, tig = lane & 3;
    const int mBase = blockIdx.y * 128, nBase = blockIdx.x * 128;

    const int am = tid >> 1;
    const int ak = (tid & 1) * 8;
    const int bk = tid >> 4;
    const int bn = (tid & 15) * 8;

    auto issue = [&](int kt, int s) {
        const float* p = A + (size_t)(mBase + am) * 512 + kt * 16 + ak;
        cp16(&As[s][am][ak],     p,     true);
        cp16(&As[s][am][ak + 4], p + 4, true);
        const float* q = W + (size_t)(kt * 16 + bk) * 512 + nBase + bn;
        cp16(&Bs[s][bk][bn],     q,     true);
        cp16(&Bs[s][bk][bn + 4], q + 4, true);
    };

    float acc[4][4][4];
#pragma unroll
    for (int i = 0; i < 4; i++)
#pragma unroll
        for (int j = 0; j < 4; j++)
#pragma unroll
            for (int c = 0; c < 4; c++) acc[i][j][c] = 0.f;

    issue(0, 0); CP_COMMIT();
    issue(1, 1); CP_COMMIT();

    const int NT = 32;
    for (int kt = 0; kt < NT; kt++) {
        const int s = kt & 1;
        if (kt + 1 < NT) { CP_WAIT(1); } else { CP_WAIT(0); }
        __syncthreads();
#pragma unroll
        for (int ks = 0; ks < 16; ks += 8) {
            unsigned afr[4][4], bfr[4][2];
#pragma unroll
            for (int mf = 0; mf < 4; mf++) {
                const int m0 = wm * 64 + mf * 16 + gid;
                afr[mf][0] = __float_as_uint(As[s][m0][ks + tig]);
                afr[mf][1] = __float_as_uint(As[s][m0 + 8][ks + tig]);
                afr[mf][2] = __float_as_uint(As[s][m0][ks + tig + 4]);
                afr[mf][3] = __float_as_uint(As[s][m0 + 8][ks + tig + 4]);
            }
#pragma unroll
            for (int nf = 0; nf < 4; nf++) {
                const int n0 = wn * 32 + nf * 8 + gid;
                bfr[nf][0] = __float_as_uint(Bs[s][ks + tig][n0]);
                bfr[nf][1] = __float_as_uint(Bs[s][ks + tig + 4][n0]);
            }
#pragma unroll
            for (int mf = 0; mf < 4; mf++)
#pragma unroll
                for (int nf = 0; nf < 4; nf++)
                    mma_tf32(acc[mf][nf], afr[mf], bfr[nf]);
        }
        __syncthreads();
        if (kt + 2 < NT) { issue(kt + 2, s); CP_COMMIT(); }
    }

#pragma unroll
    for (int mf = 0; mf < 4; mf++) {
        const int row = mBase + wm * 64 + mf * 16 + gid;
#pragma unroll
        for (int nf = 0; nf < 4; nf++) {
            const int col = nBase + wn * 32 + nf * 8 + tig * 2;
            C[(size_t)row * 512 + col]           = acc[mf][nf][0];
            C[(size_t)row * 512 + col + 1]       = acc[mf][nf][1];
            C[(size_t)(row + 8) * 512 + col]     = acc[mf][nf][2];
            C[(size_t)(row + 8) * 512 + col + 1] = acc[mf][nf][3];
        }
    }
}

// ---------------------------------------------------------------------------
// fp32 GEMM (logits): C = [A1|A2] @ W + bias, remapped out layout.
// ---------------------------------------------------------------------------
__global__ __launch_bounds__(256) void gemm_fused(
    const float* __restrict__ A1, const float* __restrict__ A2,
    const float* __restrict__ W, const float* __restrict__ bias,
    float* __restrict__ C, int N, int K)
{
    __shared__ float sA[16][65];
    __shared__ float sB[16][68];
    const int tid = threadIdx.x;
    const int tx = tid & 15, ty = tid >> 4;
    const int mBase = blockIdx.y * 64, nBase = blockIdx.x * 64;

    const int lam = tid >> 2, lak = (tid & 3) * 4;
    const int lbk = tid >> 4, lbn = (tid & 15) * 4;

    float acc[4][4];
#pragma unroll
    for (int i = 0; i < 4; i++)
#pragma unroll
        for (int j = 0; j < 4; j++) acc[i][j] = 0.f;

    for (int k0 = 0; k0 < K; k0 += 16) {
        float av[4], bv[4];
#pragma unroll
        for (int i = 0; i < 4; i++) {
            const int kk = k0 + lak + i;
            av[i] = (kk < 512) ? A1[(size_t)(mBase + lam) * 512 + kk]
                               : A2[(size_t)(mBase + lam) * 512 + kk - 512];
        }
#pragma unroll
        for (int i = 0; i < 4; i++) {
            const int nn = nBase + lbn + i;
            bv[i] = (nn < N) ? W[(size_t)(k0 + lbk) * N + nn] : 0.f;
        }
        __syncthreads();
#pragma unroll
        for (int i = 0; i < 4; i++) sA[lak + i][lam] = av[i];
#pragma unroll
        for (int i = 0; i < 4; i++) sB[lbk][lbn + i] = bv[i];
        __syncthreads();
#pragma unroll
        for (int kk = 0; kk < 16; kk++) {
            float a[4], b[4];
#pragma unroll
            for (int i = 0; i < 4; i++) a[i] = sA[kk][ty * 4 + i];
#pragma unroll
            for (int j = 0; j < 4; j++) b[j] = sB[kk][tx * 4 + j];
#pragma unroll
            for (int i = 0; i < 4; i++)
#pragma unroll
                for (int j = 0; j < 4; j++) acc[i][j] += a[i] * b[j];
        }
    }

#pragma unroll
    for (int i = 0; i < 4; i++) {
        const int row = mBase + ty * 4 + i;
#pragma unroll
        for (int j = 0; j < 4; j++) {
            const int col = nBase + tx * 4 + j;
            if (col < N) {
                const float v = acc[i][j] + bias[col];
                const int t = row >> 7, b = row & 127;
                C[(size_t)(b * TSTEPS + t) * NCLS + col] = v;
            }
        }
    }
}

// ---------------------------------------------------------------------------
// Attention logits: att[t,b,pos] = sum_ch tanh(fproj[b,pos,ch]+hp[t,b,ch])*wa[ch]
// fproj register-resident (read once). grid (8 pos-chunks, 128 b), 256 thr
// ---------------------------------------------------------------------------
__global__ __launch_bounds__(256) void att_kernel(
    const float* __restrict__ fproj, const float* __restrict__ hp,
    const float* __restrict__ wa, float* __restrict__ att)
{
    __shared__ float sHp[8 * 65];
    __shared__ float sWa[8 * 65];
    const int tid = threadIdx.x;
    const int posl = tid >> 3, tch = tid & 7;
    const int b = blockIdx.y, pos0 = blockIdx.x * 32;
    const int ch0 = tch * 64;

    float fr[64];
    const float* fp = fproj + (size_t)(b * NPOS + pos0 + posl) * 512 + ch0;
#pragma unroll
    for (int i = 0; i < 16; i++) {
        const float4 v = *(const float4*)(fp + i * 4);
        fr[i * 4 + 0] = v.x; fr[i * 4 + 1] = v.y;
        fr[i * 4 + 2] = v.z; fr[i * 4 + 3] = v.w;
    }
    for (int k = tid; k < 512; k += 256)
        sWa[(k >> 6) * 65 + (k & 63)] = wa[k];

    for (int t = 0; t < TSTEPS; t++) {
        __syncthreads();
        const float* hrow = hp + (size_t)(t * BB + b) * 512;
        for (int k = tid; k < 512; k += 256)
            sHp[(k >> 6) * 65 + (k & 63)] = hrow[k];
        __syncthreads();
        float s = 0.f;
#pragma unroll
        for (int i = 0; i < 64; i++) {
            const float x = fr[i] + sHp[tch * 65 + i];
            s += fast_tanh(x) * sWa[tch * 65 + i];
        }
        s += __shfl_down_sync(0xffffffffu, s, 4, 8);
        s += __shfl_down_sync(0xffffffffu, s, 2, 8);
        s += __shfl_down_sync(0xffffffffu, s, 1, 8);
        if (tch == 0)
            att[(size_t)(t * BB + b) * NPOS + pos0 + posl] = s;
    }
}

// ---------------------------------------------------------------------------
// Glimpse with FUSED softmax: reads raw att logits, normalizes in-block,
// then glim[t,b,c] = sum_pos softmax(att)[t,b,pos] * features[b,pos,c]
// ---------------------------------------------------------------------------
__global__ __launch_bounds__(256) void glimpse_kernel(
    const float* __restrict__ F, const float* __restrict__ attR,
    float* __restrict__ glim)
{
    __shared__ float sF[NPOS * 32];
    __shared__ float sA[NPOS];
    __shared__ float sP[8][33];
    __shared__ float rmax[8], rsum[8];
    const int tid = threadIdx.x;
    const int lane = tid & 31, wrp = tid >> 5;
    const int b = blockIdx.y, ch0 = blockIdx.x * 32;

    for (int idx = tid; idx < NPOS * 32; idx += 256) {
        const int pos = idx >> 5, ch = idx & 31;
        sF[pos * 32 + ch] = F[(size_t)(b * NPOS + pos) * 512 + ch0 + ch];
    }
    const int pg = tid >> 5, ch = tid & 31;

    for (int t = 0; t < TSTEPS; t++) {
        const float v = attR[(size_t)(t * BB + b) * NPOS + tid];
        float m = v;
#pragma unroll
        for (int o = 16; o; o >>= 1) m = fmaxf(m, __shfl_xor_sync(0xffffffffu, m, o));
        if (lane == 0) rmax[wrp] = m;
        __syncthreads();
        float M = rmax[0];
#pragma unroll
        for (int i = 1; i < 8; i++) M = fmaxf(M, rmax[i]);
        const float e = __expf(v - M);
        float s2 = e;
#pragma unroll
        for (int o = 16; o; o >>= 1) s2 += __shfl_xor_sync(0xffffffffu, s2, o);
        if (lane == 0) rsum[wrp] = s2;
        __syncthreads();
        float S = 0.f;
#pragma unroll
        for (int i = 0; i < 8; i++) S += rsum[i];
        sA[tid] = e / S;
        __syncthreads();

        float s = 0.f;
#pragma unroll
        for (int p = 0; p < 32; p++)
            s += sA[pg * 32 + p] * sF[(pg * 32 + p) * 32 + ch];
        sP[pg][ch] = s;
        __syncthreads();
        if (tid < 32) {
            float g = 0.f;
#pragma unroll
            for (int i = 0; i < 8; i++) g += sP[i][tid];
            glim[(size_t)(t * BB + b) * 512 + ch0 + tid] = g;
        }
    }
}

// ---------------------------------------------------------------------------
// Launch
// ---------------------------------------------------------------------------
extern "C" void kernel_launch(void* const* d_in, const int* in_sizes, int n_in,
                              void* d_out, int out_size)
{
    const float* features = (const float*)d_in[0];
    const float* holistic = (const float*)d_in[1];
    const int*   gt       = (const int*)  d_in[2];
    const float* embed_W  = (const float*)d_in[3];
    const float* k0   = (const float*)d_in[4];
    const float* rk0  = (const float*)d_in[5];
    const float* b0   = (const float*)d_in[6];
    const float* k1   = (const float*)d_in[7];
    const float* rk1  = (const float*)d_in[8];
    const float* b1   = (const float*)d_in[9];
    const float* Wh   = (const float*)d_in[10];
    const float* Wf   = (const float*)d_in[11];
    const float* bf   = (const float*)d_in[12];
    const float* wa   = (const float*)d_in[13];
    const float* outW = (const float*)d_in[14];
    const float* outb = (const float*)d_in[15];
    float* out = (float*)d_out;

    float* S = nullptr;
    cudaGetSymbolAddress((void**)&S, g_scratch);

    float* fproj = S + OF_FPROJ;
    float* Ek0   = S + OF_EK0;
    float* st    = S + OF_ST;
    float* h1all = S + OF_H1ALL;
    float* hp    = S + OF_HP;
    float* att   = S + OF_ATT;
    float* glim  = S + OF_GLIM;
    __half* k0t  = (__half*)(S + OF_WT);
    __half* rk0t = k0t + 1048576;
    __half* k1t  = k0t + 2097152;
    __half* rk1t = k0t + 3145728;
    __half* Fh   = (__half*)(S + OF_FH);
    __half* Wth  = (__half*)(S + OF_WTH);

    cudaFuncSetAttribute(fused_conv_chain,
        cudaFuncAttributeMaxDynamicSharedMemorySize, CONV_SMEM);

    // prep: fp16 conversions, fp16 gate-interleaved transposed LSTM weights
    prep_half<<<65536 + 2304, 256>>>(features, Wf, Fh, Wth);
    reorder_w4h<<<dim3(2048, 4), 256>>>(k0, rk0, k1, rk1, k0t);
    ek0_kernel<<<dim3(8, 112), 256>>>(embed_W, k0, Ek0);

    // fp16 conv (BK=64, ldmatrix) + pipelined LSTM chain in ONE launch
    fused_conv_chain<<<128 + 1024, 256, CONV_SMEM>>>(
        Fh, Wth, bf, fproj,
        Ek0, gt, holistic, k0t, rk0t, k1t, rk1t, b0, b1, st, h1all);

    // batched epilogue over all 31 steps (softmax fused into glimpse)
    gemm_tc<<<dim3(4, 31), 256>>>(h1all, Wh, hp);
    att_kernel<<<dim3(8, 128), 256>>>(fproj, hp, wa, att);
    glimpse_kernel<<<dim3(16, 128), 256>>>(features, att, glim);
    gemm_fused<<<dim3(2, 62), 256>>>(h1all, glim, outW, outb, out, NCLS, 1024);
}